// round 17
// baseline (speedup 1.0000x reference)
#include <cuda_runtime.h>
#include <cuda_bf16.h>
#include <cstdint>

#define LVL   32
#define PINS  131072
#define NNETS 1000000
#define TPER  10.0f

// Per-arc validity (bit0 = arc0 valid, bit1 = arc1 valid).
__device__ unsigned char g_valid[(LVL - 1) * PINS];

static __device__ __forceinline__ void atomicMinFloat(float* addr, float val) {
    if (val >= 0.0f) {
        atomicMin((int*)addr, __float_as_int(val));
    } else {
        atomicMax((unsigned int*)addr, __float_as_uint(val));
    }
}

// ---- preA (s0): valid bits (all rows) + arr[0] ----
__global__ void sta_preA_kernel(const float* __restrict__ delays,
                                const int2*  __restrict__ net,
                                const unsigned int* __restrict__ mask,
                                float* __restrict__ arr) {
    int i = blockIdx.x * blockDim.x + threadIdx.x;
    if (i < (LVL - 1) * PINS) {
        int2 n = __ldg(&net[i]);
        unsigned v0 = (mask[n.x] == 0u) ? 1u : 0u;
        unsigned v1 = (mask[n.y] == 0u) ? 2u : 0u;
        g_valid[i] = (unsigned char)(v0 | v1);
    }
    if (i < PINS) arr[i] = delays[i];
}

// ---- preB (s2): req init + mask re-emit ----
__global__ void sta_preB_kernel(const unsigned int* __restrict__ mask,
                                float* __restrict__ req,
                                float* __restrict__ mask_out,
                                long long mask_out_room) {
    int i = blockIdx.x * blockDim.x + threadIdx.x;
    if (i < LVL * PINS) req[i] = TPER;
    if (i < NNETS && i < mask_out_room) mask_out[i] = mask[i] ? 1.0f : 0.0f;
}

// ---- forward level l: 2 pins/thread, PDL (GDS then trigger) ----
__global__ void sta_fwd_kernel(const float* __restrict__ delays,
                               const int2*  __restrict__ src,
                               float* __restrict__ arr,
                               int l) {
    int t = blockIdx.x * blockDim.x + threadIdx.x;
    if (t >= PINS / 2) return;

    float2 d  = ((const float2*)(delays + l * PINS))[t];
    int4   s  = ((const int4*)(src + (l - 1) * PINS))[t];
    uchar2 vv = ((const uchar2*)(g_valid + (l - 1) * PINS))[t];

#if __CUDA_ARCH__ >= 900
    cudaGridDependencySynchronize();
    cudaTriggerProgrammaticLaunchCompletion();
#endif

    const float* ap = arr + (l - 1) * PINS;
    float a0 = (vv.x & 1u) ? __ldg(&ap[s.x]) : 0.0f;
    float a1 = (vv.x & 2u) ? __ldg(&ap[s.y]) : 0.0f;
    float b0 = (vv.y & 1u) ? __ldg(&ap[s.z]) : 0.0f;
    float b1 = (vv.y & 2u) ? __ldg(&ap[s.w]) : 0.0f;

    float m0 = d.x;
    if (vv.x & 1u) m0 = fmaxf(m0, a0 + d.x);
    if (vv.x & 2u) m0 = fmaxf(m0, a1 + d.x);
    float m1 = d.y;
    if (vv.y & 1u) m1 = fmaxf(m1, b0 + d.y);
    if (vv.y & 2u) m1 = fmaxf(m1, b1 + d.y);

    ((float2*)(arr + l * PINS))[t] = make_float2(m0, m1);
}

// ---- backward level l: scatter-min into req[l], PDL ----
__global__ void sta_bwd_kernel(const float* __restrict__ delays,
                               const int2*  __restrict__ src,
                               float* __restrict__ req,
                               int l) {
    int t = blockIdx.x * blockDim.x + threadIdx.x;
    if (t >= PINS / 2) return;

    const int up = (l + 1) * PINS;
    float2 d1 = ((const float2*)(delays + up))[t];
    int4   s  = ((const int4*)(src + l * PINS))[t];
    uchar2 vv = ((const uchar2*)(g_valid + l * PINS))[t];

#if __CUDA_ARCH__ >= 900
    cudaGridDependencySynchronize();
    cudaTriggerProgrammaticLaunchCompletion();
#endif

    float2 r1 = __ldcg((const float2*)(req + up) + t);
    float c0 = r1.x - d1.x;
    float c1 = r1.y - d1.y;

    float* rl = req + (long long)l * PINS;
    if (vv.x & 1u) atomicMinFloat(rl + s.x, c0);
    if (vv.x & 2u) atomicMinFloat(rl + s.y, c0);
    if (vv.y & 1u) atomicMinFloat(rl + s.z, c1);
    if (vv.y & 2u) atomicMinFloat(rl + s.w, c1);
}

// ---- epilogue: slack for ALL levels (both chains complete here) ----
__global__ void sta_epilogue_kernel(const float* __restrict__ arr,
                                    const float* __restrict__ req,
                                    float* __restrict__ slack) {
    int t = blockIdx.x * blockDim.x + threadIdx.x;
    if (t >= LVL * PINS / 2) return;
    float2 r = ((const float2*)req)[t];
    float2 a = ((const float2*)arr)[t];
    ((float2*)slack)[t] = make_float2(r.x - a.x, r.y - a.y);
}

// ---------------------------------------------------------------------------
template <typename... Args>
static void launch_pdl(cudaStream_t st, dim3 grid, dim3 block, bool pdl,
                       void (*kern)(Args...), Args... args) {
    cudaLaunchConfig_t cfg = {};
    cfg.gridDim = grid;
    cfg.blockDim = block;
    cfg.stream = st;
    cudaLaunchAttribute at[1];
    if (pdl) {
        at[0].id = cudaLaunchAttributeProgrammaticStreamSerialization;
        at[0].val.programmaticStreamSerializationAllowed = 1;
        cfg.attrs = at;
        cfg.numAttrs = 1;
    }
    cudaLaunchKernelEx(&cfg, kern, args...);
}

extern "C" void kernel_launch(void* const* d_in, const int* in_sizes, int n_in,
                              void* d_out, int out_size) {
    const float*        delays = (const float*)d_in[0];
    const int2*         src    = (const int2*)d_in[1];
    const int2*         net    = (const int2*)d_in[2];
    const unsigned int* mask   = (const unsigned int*)d_in[3];

    float* out = (float*)d_out;
    const long long LP = (long long)LVL * PINS;

    float* arr      = out;           // [0,   LP)
    float* req      = out + LP;      // [LP,  2LP)
    float* slack    = out + 2 * LP;  // [2LP, 3LP)
    float* mask_out = out + 3 * LP;  // [3LP, 3LP+NNETS)
    long long mask_room = (long long)out_size - 3 * LP;

    cudaStream_t s0 = (cudaStream_t)0;   // harness/capture stream

    // Static handles: created once on the first (pre-capture) call so the
    // device-memory baseline includes them -> no post-teardown delta.
    static cudaStream_t s2 = nullptr;
    static cudaEvent_t evFork = nullptr, evA = nullptr, evBwd = nullptr;
    if (!s2) {
        cudaStreamCreateWithFlags(&s2, cudaStreamNonBlocking);
        cudaEventCreateWithFlags(&evFork, cudaEventDisableTiming);
        cudaEventCreateWithFlags(&evA,    cudaEventDisableTiming);
        cudaEventCreateWithFlags(&evBwd,  cudaEventDisableTiming);
    }

    const int T = 128;
    const int blocksH = (PINS / 2 + T - 1) / T;          // 512

    // fork s2 from capture origin
    cudaEventRecord(evFork, s0);
    cudaStreamWaitEvent(s2, evFork, 0);

    // s0: preA (valid bits + arr[0])
    {
        int bA = ((LVL - 1) * PINS + 255) / 256;
        sta_preA_kernel<<<bA, 256, 0, s0>>>(delays, net, mask, arr);
        cudaEventRecord(evA, s0);
    }

    // s0: forward chain, PDL-overlapped, no mid-chain events
    for (int l = 1; l < LVL; ++l)
        launch_pdl(s0, dim3(blocksH), dim3(T), true,
                   sta_fwd_kernel, delays, src, arr, l);

    // s2: preB, then backward chain (needs g_valid -> evA); fully hidden
    {
        int bB = (int)((LP + 255) / 256);
        sta_preB_kernel<<<bB, 256, 0, s2>>>(mask, req, mask_out, mask_room);
        cudaStreamWaitEvent(s2, evA, 0);
        for (int l = LVL - 2; l >= 0; --l)
            launch_pdl(s2, dim3(blocksH), dim3(T), l != LVL - 2,
                       sta_bwd_kernel, delays, src, req, l);
        cudaEventRecord(evBwd, s2);
    }

    // join at the very end, then slack for all levels
    cudaStreamWaitEvent(s0, evBwd, 0);
    {
        int blocksE = (int)((LP / 2 + 255) / 256);
        sta_epilogue_kernel<<<blocksE, 256, 0, s0>>>(arr, req, slack);
    }
}